// round 1
// baseline (speedup 1.0000x reference)
#include <cuda_runtime.h>
#include <math.h>

#define V_ 371
#define E_ 512
#define H_ 8
#define L_ 8
#define B_ 4
#define T_ 1024
#define D_ 64

// ---------------- scratch (static device globals; no allocation) ----------------
__device__ float g_x[B_ * T_ * E_];          // residual stream   8 MB
__device__ float g_h[B_ * T_ * E_];          // LN output         8 MB
__device__ float g_qkv[B_ * T_ * 3 * E_];    // qkv               24 MB
__device__ float g_att[B_ * H_ * T_ * T_];   // scores/probs      128 MB
__device__ float g_y[B_ * T_ * E_];          // attn out          8 MB
__device__ float g_h2[B_ * T_ * 4 * E_];     // MLP hidden        32 MB

// ---------------- generic batched tiled GEMM ----------------
// C[m,n] = epi( alpha * sum_k A[m,k] * (transB ? B[n,k] : B[k,n]) )
// EPI: 0 = none, 1 = exact GELU, 2 = add residual (Add, same layout as C)
// batching: z = blockIdx.z; ptr += (z/zdiv)*s1 + (z%zdiv)*s2
// causal: 1 = skip tiles fully above diagonal (square tiles), 2 = clamp K to row0+BM
template <int BM, int BN, int BK, int TM, int TN, int EPI>
__global__ void __launch_bounds__((BM / TM) * (BN / TN))
gemm_k(const float* __restrict__ A, const float* __restrict__ Bm,
       const float* __restrict__ Add, float* __restrict__ C,
       int M, int N, int K, int lda, int ldb, int ldc,
       float alpha, int transB, int causal, int zdiv,
       long long sA1, long long sA2, long long sB1, long long sB2,
       long long sC1, long long sC2) {
    constexpr int NT = (BM / TM) * (BN / TN);
    __shared__ float As[BK][BM + 4];
    __shared__ float Bs[BK][BN];

    int z = blockIdx.z;
    long long zq = z / zdiv, zr = z % zdiv;
    A += zq * sA1 + zr * sA2;
    Bm += zq * sB1 + zr * sB2;
    C += zq * sC1 + zr * sC2;
    if (EPI == 2) Add += zq * sC1 + zr * sC2;

    int row0 = blockIdx.y * BM;
    int col0 = blockIdx.x * BN;
    if (causal == 1 && col0 > row0 + BM - 1) return;
    int Keff = (causal == 2) ? ((row0 + BM < K) ? row0 + BM : K) : K;

    int tid = threadIdx.x;
    int tx = tid % (BN / TN);
    int ty = tid / (BN / TN);

    float acc[TM][TN];
#pragma unroll
    for (int i = 0; i < TM; i++)
#pragma unroll
        for (int j = 0; j < TN; j++) acc[i][j] = 0.f;

    for (int k0 = 0; k0 < Keff; k0 += BK) {
        // ---- load A tile: As[k][m] ----
#pragma unroll
        for (int t = tid; t < BM * BK / 4; t += NT) {
            int m = t / (BK / 4);
            int kq = (t % (BK / 4)) * 4;
            float4 v = make_float4(0.f, 0.f, 0.f, 0.f);
            int gr = row0 + m;
            if (gr < M)
                v = *reinterpret_cast<const float4*>(&A[(long long)gr * lda + k0 + kq]);
            As[kq + 0][m] = v.x;
            As[kq + 1][m] = v.y;
            As[kq + 2][m] = v.z;
            As[kq + 3][m] = v.w;
        }
        // ---- load B tile: Bs[k][n] ----
        if (!transB) {
#pragma unroll
            for (int t = tid; t < BK * BN / 4; t += NT) {
                int k = t / (BN / 4);
                int nq = (t % (BN / 4)) * 4;
                int gc = col0 + nq;
                float4 v = make_float4(0.f, 0.f, 0.f, 0.f);
                const float* src = &Bm[(long long)(k0 + k) * ldb + gc];
                if (gc + 3 < N) {
                    v = *reinterpret_cast<const float4*>(src);
                } else {
                    if (gc + 0 < N) v.x = src[0];
                    if (gc + 1 < N) v.y = src[1];
                    if (gc + 2 < N) v.z = src[2];
                    if (gc + 3 < N) v.w = src[3];
                }
                *reinterpret_cast<float4*>(&Bs[k][nq]) = v;
            }
        } else {
#pragma unroll
            for (int t = tid; t < BN * BK / 4; t += NT) {
                int n = t / (BK / 4);
                int kq = (t % (BK / 4)) * 4;
                int gc = col0 + n;
                float4 v = make_float4(0.f, 0.f, 0.f, 0.f);
                if (gc < N)
                    v = *reinterpret_cast<const float4*>(&Bm[(long long)gc * ldb + k0 + kq]);
                Bs[kq + 0][n] = v.x;
                Bs[kq + 1][n] = v.y;
                Bs[kq + 2][n] = v.z;
                Bs[kq + 3][n] = v.w;
            }
        }
        __syncthreads();

#pragma unroll
        for (int kk = 0; kk < BK; kk++) {
            float a[TM], b[TN];
            const float4* a4 = reinterpret_cast<const float4*>(&As[kk][ty * TM]);
            const float4* b4 = reinterpret_cast<const float4*>(&Bs[kk][tx * TN]);
#pragma unroll
            for (int i = 0; i < TM / 4; i++) {
                float4 v = a4[i];
                a[4 * i] = v.x; a[4 * i + 1] = v.y; a[4 * i + 2] = v.z; a[4 * i + 3] = v.w;
            }
#pragma unroll
            for (int j = 0; j < TN / 4; j++) {
                float4 v = b4[j];
                b[4 * j] = v.x; b[4 * j + 1] = v.y; b[4 * j + 2] = v.z; b[4 * j + 3] = v.w;
            }
#pragma unroll
            for (int i = 0; i < TM; i++)
#pragma unroll
                for (int j = 0; j < TN; j++) acc[i][j] += a[i] * b[j];
        }
        __syncthreads();
    }

    // ---- epilogue ----
#pragma unroll
    for (int i = 0; i < TM; i++) {
        int r = row0 + ty * TM + i;
        if (r >= M) continue;
#pragma unroll
        for (int j = 0; j < TN; j++) {
            int c = col0 + tx * TN + j;
            if (c >= N) continue;
            float v = acc[i][j] * alpha;
            if (EPI == 1) v = 0.5f * v * (1.f + erff(v * 0.70710678118654752440f));
            if (EPI == 2) v += Add[(long long)r * ldc + c];
            C[(long long)r * ldc + c] = v;
        }
    }
}

// ---------------- embedding: x = wte[idx] + wpe ----------------
__global__ void embed_kernel(const int* __restrict__ idx,
                             const float* __restrict__ wte,
                             const float* __restrict__ wpe,
                             float* __restrict__ out) {
    int t = blockIdx.x;          // 0..B*T-1
    int pos = t % T_;
    int id = idx[t];
    float4 a = reinterpret_cast<const float4*>(wte + (long long)id * E_)[threadIdx.x];
    float4 b = reinterpret_cast<const float4*>(wpe + (long long)pos * E_)[threadIdx.x];
    float4 o;
    o.x = a.x + b.x; o.y = a.y + b.y; o.z = a.z + b.z; o.w = a.w + b.w;
    reinterpret_cast<float4*>(out + (long long)t * E_)[threadIdx.x] = o;
}

// ---------------- LayerNorm (weight only, eps=1e-5) ----------------
__global__ void ln_kernel(const float* __restrict__ x, const float* __restrict__ w,
                          float* __restrict__ out) {
    int row = blockIdx.x;  // 0..B*T-1, 128 threads, E=512 -> one float4 each
    float4 v = reinterpret_cast<const float4*>(x + (long long)row * E_)[threadIdx.x];
    float s = v.x + v.y + v.z + v.w;
    float ss = v.x * v.x + v.y * v.y + v.z * v.z + v.w * v.w;
    __shared__ float sh[8];
#pragma unroll
    for (int o = 16; o > 0; o >>= 1) {
        s += __shfl_down_sync(0xffffffffu, s, o);
        ss += __shfl_down_sync(0xffffffffu, ss, o);
    }
    int wid = threadIdx.x >> 5, lane = threadIdx.x & 31;
    if (lane == 0) { sh[wid] = s; sh[4 + wid] = ss; }
    __syncthreads();
    if (threadIdx.x == 0) {
        float ts = sh[0] + sh[1] + sh[2] + sh[3];
        float tss = sh[4] + sh[5] + sh[6] + sh[7];
        float m = ts * (1.f / E_);
        float var = tss * (1.f / E_) - m * m;
        sh[0] = m;
        sh[1] = rsqrtf(var + 1e-5f);
    }
    __syncthreads();
    float m = sh[0], r = sh[1];
    float4 wv = reinterpret_cast<const float4*>(w)[threadIdx.x];
    float4 o;
    o.x = (v.x - m) * r * wv.x;
    o.y = (v.y - m) * r * wv.y;
    o.z = (v.z - m) * r * wv.z;
    o.w = (v.w - m) * r * wv.w;
    reinterpret_cast<float4*>(out + (long long)row * E_)[threadIdx.x] = o;
}

// ---------------- causal softmax over row i (valid j in [0,i]) ----------------
// Normalizes j<=i, zero-fills (i, block_end) so att@v can run to the 128 boundary.
__global__ void softmax_kernel(float* __restrict__ S) {
    int i = blockIdx.x;
    float* row = S + (long long)blockIdx.y * T_ * T_ + (long long)i * T_;
    int n = i + 1;
    __shared__ float sh[8];
    int tid = threadIdx.x, lane = tid & 31, wid = tid >> 5;

    float m = -3.4e38f;
    for (int j = tid; j < n; j += 128) m = fmaxf(m, row[j]);
#pragma unroll
    for (int o = 16; o > 0; o >>= 1) m = fmaxf(m, __shfl_xor_sync(0xffffffffu, m, o));
    if (lane == 0) sh[wid] = m;
    __syncthreads();
    m = fmaxf(fmaxf(sh[0], sh[1]), fmaxf(sh[2], sh[3]));

    float s = 0.f;
    for (int j = tid; j < n; j += 128) {
        float e = expf(row[j] - m);
        row[j] = e;
        s += e;
    }
#pragma unroll
    for (int o = 16; o > 0; o >>= 1) s += __shfl_xor_sync(0xffffffffu, s, o);
    if (lane == 0) sh[4 + wid] = s;
    __syncthreads();
    s = sh[4] + sh[5] + sh[6] + sh[7];
    float inv = 1.f / s;
    for (int j = tid; j < n; j += 128) row[j] *= inv;

    int zend = ((i >> 7) + 1) << 7;  // end of this row's 128-block
    for (int j = n + tid; j < zend; j += 128) row[j] = 0.f;
}

// ---------------- host-side pipeline ----------------
extern "C" void kernel_launch(void* const* d_in, const int* in_sizes, int n_in,
                              void* d_out, int out_size) {
    (void)in_sizes; (void)n_in; (void)out_size;
    const int* idx = (const int*)d_in[0];
    const float* wte = (const float*)d_in[1];
    const float* wpe = (const float*)d_in[2];
    const float* aw = (const float*)d_in[3];
    const float* pw = (const float*)d_in[4];
    const float* fw = (const float*)d_in[5];
    const float* fpw = (const float*)d_in[6];
    const float* l1 = (const float*)d_in[7];
    const float* l2 = (const float*)d_in[8];
    const float* lnf = (const float*)d_in[9];
    float* out = (float*)d_out;

    float *gx, *gh, *gqkv, *gatt, *gy, *gh2;
    cudaGetSymbolAddress((void**)&gx, g_x);
    cudaGetSymbolAddress((void**)&gh, g_h);
    cudaGetSymbolAddress((void**)&gqkv, g_qkv);
    cudaGetSymbolAddress((void**)&gatt, g_att);
    cudaGetSymbolAddress((void**)&gy, g_y);
    cudaGetSymbolAddress((void**)&gh2, g_h2);

    const long long Z = 0;
    const long long sQKV = (long long)T_ * 3 * E_;   // per-batch stride in qkv
    const long long sATT1 = (long long)H_ * T_ * T_; // per-batch stride in att
    const long long sATT2 = (long long)T_ * T_;      // per-head stride in att

    embed_kernel<<<B_ * T_, 128>>>(idx, wte, wpe, gx);

    for (int l = 0; l < L_; l++) {
        // h = LN(x, ln1)
        ln_kernel<<<B_ * T_, 128>>>(gx, l1 + (long long)l * E_, gh);
        // qkv = h @ aw[l]   [4096,512]@[512,1536]
        gemm_k<128, 128, 8, 8, 8, 0><<<dim3(12, 32, 1), 256>>>(
            gh, aw + (long long)l * E_ * 3 * E_, nullptr, gqkv,
            4096, 1536, 512, 512, 1536, 1536, 1.f, 0, 0, 1, Z, Z, Z, Z, Z, Z);
        // S = scale * q @ k^T, per (b,h); skip tiles above diagonal
        gemm_k<128, 128, 8, 8, 8, 0><<<dim3(8, 8, B_ * H_), 256>>>(
            gqkv, gqkv + E_, nullptr, gatt,
            1024, 1024, 64, 3 * E_, 3 * E_, 1024, 0.125f, 1, 1, H_,
            sQKV, 64, sQKV, 64, sATT1, sATT2);
        // causal softmax
        softmax_kernel<<<dim3(T_, B_ * H_), 128>>>(gatt);
        // y = att @ v, per (b,h); K clamped to causal block boundary
        gemm_k<128, 64, 8, 8, 8, 0><<<dim3(1, 8, B_ * H_), 128>>>(
            gatt, gqkv + 2 * E_, nullptr, gy,
            1024, 64, 1024, 1024, 3 * E_, 512, 1.f, 0, 2, H_,
            sATT1, sATT2, sQKV, 64, (long long)T_ * E_, 64);
        // x = x + y @ pw[l]
        gemm_k<128, 128, 8, 8, 8, 2><<<dim3(4, 32, 1), 256>>>(
            gy, pw + (long long)l * E_ * E_, gx, gx,
            4096, 512, 512, 512, 512, 512, 1.f, 0, 0, 1, Z, Z, Z, Z, Z, Z);
        // h = LN(x, ln2)
        ln_kernel<<<B_ * T_, 128>>>(gx, l2 + (long long)l * E_, gh);
        // h2 = gelu(h @ fw[l])   [4096,512]@[512,2048]
        gemm_k<128, 128, 8, 8, 8, 1><<<dim3(16, 32, 1), 256>>>(
            gh, fw + (long long)l * E_ * 4 * E_, nullptr, gh2,
            4096, 2048, 512, 512, 2048, 2048, 1.f, 0, 0, 1, Z, Z, Z, Z, Z, Z);
        // x = x + h2 @ fpw[l]    [4096,2048]@[2048,512]
        gemm_k<128, 128, 8, 8, 8, 2><<<dim3(4, 32, 1), 256>>>(
            gh2, fpw + (long long)l * 4 * E_ * E_, gx, gx,
            4096, 512, 2048, 2048, 512, 512, 1.f, 0, 0, 1, Z, Z, Z, Z, Z, Z);
    }

    // final LN + tied logits: out = LN(x) @ wte^T   [4096,512]@[371,512]^T
    ln_kernel<<<B_ * T_, 128>>>(gx, lnf, gh);
    gemm_k<128, 128, 8, 8, 8, 0><<<dim3(3, 32, 1), 256>>>(
        gh, wte, nullptr, out,
        4096, 371, 512, 512, 512, 371, 1.f, 1, 0, 1, Z, Z, Z, Z, Z, Z);
}

// round 4
// speedup vs baseline: 1.9368x; 1.9368x over previous
#include <cuda_runtime.h>
#include <cuda_bf16.h>
#include <math.h>
#include <stdint.h>

#define V_ 371
#define E_ 512
#define H_ 8
#define L_ 8
#define B_ 4
#define T_ 1024
#define D_ 64

// ---------------- scratch (static device globals; no allocation) ----------------
__device__ __align__(256) float g_x[B_ * T_ * E_];
__device__ __align__(256) float g_h[B_ * T_ * E_];
__device__ __align__(256) float g_qkv[B_ * T_ * 3 * E_];
__device__ __align__(256) float g_att[B_ * H_ * T_ * T_];
__device__ __align__(256) float g_y[B_ * T_ * E_];
__device__ __align__(256) float g_h2[B_ * T_ * 4 * E_];

// bf16 split buffers (activations)
__device__ __align__(256) __nv_bfloat16 g_ah[B_ * T_ * 4 * E_];
__device__ __align__(256) __nv_bfloat16 g_al[B_ * T_ * 4 * E_];
// weights, [N,K] K-major per layer, hi & lo
#define OFF_AW 0
#define SZ_AW (L_ * 3 * E_ * E_)
#define OFF_PW (OFF_AW + SZ_AW)
#define SZ_PW (L_ * E_ * E_)
#define OFF_FW (OFF_PW + SZ_PW)
#define SZ_FW (L_ * 4 * E_ * E_)
#define OFF_FPW (OFF_FW + SZ_FW)
#define SZ_FPW (L_ * E_ * 4 * E_)
#define OFF_WTE (OFF_FPW + SZ_FPW)
#define SZ_WTE_PAD (384 * E_)   /* 371 rows used, padded to 384 (3 x 128 tiles) */
#define SZ_WALL (OFF_WTE + SZ_WTE_PAD)
__device__ __align__(256) __nv_bfloat16 g_wh[SZ_WALL];
__device__ __align__(256) __nv_bfloat16 g_wl[SZ_WALL];

// =================================================================
//                        small PTX helpers
// =================================================================
__device__ __forceinline__ uint32_t smem_u32(const void* p) {
    uint32_t a;
    asm("{ .reg .u64 t; cvta.to.shared.u64 t, %1; cvt.u32.u64 %0, t; }" : "=r"(a) : "l"(p));
    return a;
}
__device__ __forceinline__ void cpa16(void* sdst, const void* gsrc) {
    uint32_t s = smem_u32(sdst);
    asm volatile("cp.async.cg.shared.global [%0], [%1], 16;" :: "r"(s), "l"(gsrc));
}
__device__ __forceinline__ void mma_bf16(float* c, const uint32_t* a, const uint32_t* b) {
    asm volatile(
        "mma.sync.aligned.m16n8k16.row.col.f32.bf16.bf16.f32 "
        "{%0,%1,%2,%3}, {%4,%5,%6,%7}, {%8,%9}, {%0,%1,%2,%3};"
        : "+f"(c[0]), "+f"(c[1]), "+f"(c[2]), "+f"(c[3])
        : "r"(a[0]), "r"(a[1]), "r"(a[2]), "r"(a[3]), "r"(b[0]), "r"(b[1]));
}

// =================================================================
//   HMMA split-bf16 GEMM: C[M,N] = A[M,K] @ B[N,K]^T (+epi)
//   A hi/lo [M,K] bf16, B hi/lo [N,K] bf16 (both K-contiguous).
//   3-term: AhBh + AhBl + AlBh, fp32 accumulate.
//   EPI: 0 none, 1 exact GELU, 2 residual add
//   CTA 128x128, 256 thr, BK=32, cp.async double buffer.
// =================================================================
#define SROW 40                       /* padded row length in halves */
#define STILE (128 * SROW)            /* halves per tile */
#define SMEM_MMA_BYTES (2 * 4 * STILE * 2)

template <int EPI>
__global__ void __launch_bounds__(256)
gemm_mma(const __nv_bfloat16* __restrict__ Ah, const __nv_bfloat16* __restrict__ Al,
         const __nv_bfloat16* __restrict__ Bh, const __nv_bfloat16* __restrict__ Bl,
         const float* __restrict__ Add, float* __restrict__ C,
         int N, int K, int ldc) {
    extern __shared__ __nv_bfloat16 smh[];
    int tid = threadIdx.x;
    int wid = tid >> 5, lane = tid & 31;
    int wm = wid >> 1, wn = wid & 1;
    int lr = lane >> 2, lc = lane & 3;

    int m0 = blockIdx.y * 128;
    int n0 = blockIdx.x * 128;

    const __nv_bfloat16* srcs[4] = {
        Ah + (size_t)m0 * K, Al + (size_t)m0 * K,
        Bh + (size_t)n0 * K, Bl + (size_t)n0 * K};

    int lrow = tid >> 1;          // 0..127
    int q0 = (tid & 1) * 2;       // 0 or 2 (two float4 chunks each)

    int nch = K >> 5;             // K / 32

    // prologue: stage 0
    {
#pragma unroll
        for (int t = 0; t < 4; t++) {
            const __nv_bfloat16* sp = srcs[t] + (size_t)lrow * K;
            __nv_bfloat16* dp = smh + t * STILE + lrow * SROW;
            cpa16(dp + q0 * 8, sp + q0 * 8);
            cpa16(dp + (q0 + 1) * 8, sp + (q0 + 1) * 8);
        }
        asm volatile("cp.async.commit_group;");
    }

    float acc[2][8][4];
#pragma unroll
    for (int i = 0; i < 2; i++)
#pragma unroll
        for (int j = 0; j < 8; j++)
#pragma unroll
            for (int r = 0; r < 4; r++) acc[i][j][r] = 0.f;

    for (int c = 0; c < nch; c++) {
        if (c + 1 < nch) {
            int k0 = (c + 1) << 5;
            __nv_bfloat16* sb = smh + ((c + 1) & 1) * 4 * STILE;
#pragma unroll
            for (int t = 0; t < 4; t++) {
                const __nv_bfloat16* sp = srcs[t] + (size_t)lrow * K + k0;
                __nv_bfloat16* dp = sb + t * STILE + lrow * SROW;
                cpa16(dp + q0 * 8, sp + q0 * 8);
                cpa16(dp + (q0 + 1) * 8, sp + (q0 + 1) * 8);
            }
            asm volatile("cp.async.commit_group;");
            asm volatile("cp.async.wait_group 1;");
        } else {
            asm volatile("cp.async.wait_group 0;");
        }
        __syncthreads();

        const __nv_bfloat16* tb = smh + (c & 1) * 4 * STILE;
        const __nv_bfloat16* pAh = tb;
        const __nv_bfloat16* pAl = tb + STILE;
        const __nv_bfloat16* pBh = tb + 2 * STILE;
        const __nv_bfloat16* pBl = tb + 3 * STILE;

#pragma unroll
        for (int ks = 0; ks < 2; ks++) {
            int kc = ks * 16 + lc * 2;
            uint32_t ah[2][4], bh[8][2];
#pragma unroll
            for (int i = 0; i < 2; i++) {
                const __nv_bfloat16* p = pAh + (wm * 32 + i * 16 + lr) * SROW + kc;
                ah[i][0] = *(const uint32_t*)p;
                ah[i][1] = *(const uint32_t*)(p + 8 * SROW);
                ah[i][2] = *(const uint32_t*)(p + 8);
                ah[i][3] = *(const uint32_t*)(p + 8 * SROW + 8);
            }
#pragma unroll
            for (int j = 0; j < 8; j++) {
                const __nv_bfloat16* p = pBh + (wn * 64 + j * 8 + lr) * SROW + kc;
                bh[j][0] = *(const uint32_t*)p;
                bh[j][1] = *(const uint32_t*)(p + 8);
            }
            // term 1: Ah x Bh
#pragma unroll
            for (int i = 0; i < 2; i++)
#pragma unroll
                for (int j = 0; j < 8; j++) mma_bf16(acc[i][j], ah[i], bh[j]);
            // term 2: Ah x Bl
            {
                uint32_t bl[8][2];
#pragma unroll
                for (int j = 0; j < 8; j++) {
                    const __nv_bfloat16* p = pBl + (wn * 64 + j * 8 + lr) * SROW + kc;
                    bl[j][0] = *(const uint32_t*)p;
                    bl[j][1] = *(const uint32_t*)(p + 8);
                }
#pragma unroll
                for (int i = 0; i < 2; i++)
#pragma unroll
                    for (int j = 0; j < 8; j++) mma_bf16(acc[i][j], ah[i], bl[j]);
            }
            // term 3: Al x Bh
            {
                uint32_t al[2][4];
#pragma unroll
                for (int i = 0; i < 2; i++) {
                    const __nv_bfloat16* p = pAl + (wm * 32 + i * 16 + lr) * SROW + kc;
                    al[i][0] = *(const uint32_t*)p;
                    al[i][1] = *(const uint32_t*)(p + 8 * SROW);
                    al[i][2] = *(const uint32_t*)(p + 8);
                    al[i][3] = *(const uint32_t*)(p + 8 * SROW + 8);
                }
#pragma unroll
                for (int i = 0; i < 2; i++)
#pragma unroll
                    for (int j = 0; j < 8; j++) mma_bf16(acc[i][j], al[i], bh[j]);
            }
        }
        __syncthreads();
    }

    // ---- epilogue ----
    bool vec_ok = ((ldc & 1) == 0);   // float2 stores only if row stride is 8B-aligned
#pragma unroll
    for (int i = 0; i < 2; i++) {
        int rbase = m0 + wm * 32 + i * 16 + lr;
#pragma unroll
        for (int half = 0; half < 2; half++) {
            int r = rbase + half * 8;
            float* crow = C + (size_t)r * ldc;
            const float* arow = (EPI == 2) ? (Add + (size_t)r * ldc) : nullptr;
#pragma unroll
            for (int j = 0; j < 8; j++) {
                int col = n0 + wn * 64 + j * 8 + lc * 2;
                float v0 = acc[i][j][half * 2 + 0];
                float v1 = acc[i][j][half * 2 + 1];
                if (EPI == 1) {
                    v0 = 0.5f * v0 * (1.f + erff(v0 * 0.70710678118654752440f));
                    v1 = 0.5f * v1 * (1.f + erff(v1 * 0.70710678118654752440f));
                }
                if (vec_ok && col + 1 < N) {
                    if (EPI == 2) { v0 += arow[col]; v1 += arow[col + 1]; }
                    *reinterpret_cast<float2*>(crow + col) = make_float2(v0, v1);
                } else {
                    if (col < N) {
                        if (EPI == 2) v0 += arow[col];
                        crow[col] = v0;
                    }
                    if (col + 1 < N) {
                        if (EPI == 2) v1 += arow[col + 1];
                        crow[col + 1] = v1;
                    }
                }
            }
        }
    }
}

// ---------------- fp32 -> bf16 hi/lo split, elementwise ----------------
__global__ void split_act(const float4* __restrict__ x, __nv_bfloat16* __restrict__ hi,
                          __nv_bfloat16* __restrict__ lo, int n4) {
    int i = blockIdx.x * blockDim.x + threadIdx.x;
    if (i >= n4) return;
    float4 v = x[i];
    __nv_bfloat16 h0 = __float2bfloat16(v.x), h1 = __float2bfloat16(v.y);
    __nv_bfloat16 h2 = __float2bfloat16(v.z), h3 = __float2bfloat16(v.w);
    __nv_bfloat162* hp = reinterpret_cast<__nv_bfloat162*>(hi);
    __nv_bfloat162* lp = reinterpret_cast<__nv_bfloat162*>(lo);
    hp[2 * i] = __nv_bfloat162(h0, h1);
    hp[2 * i + 1] = __nv_bfloat162(h2, h3);
    lp[2 * i] = __nv_bfloat162(__float2bfloat16(v.x - __bfloat162float(h0)),
                               __float2bfloat16(v.y - __bfloat162float(h1)));
    lp[2 * i + 1] = __nv_bfloat162(__float2bfloat16(v.z - __bfloat162float(h2)),
                                   __float2bfloat16(v.w - __bfloat162float(h3)));
}

// ---------------- weight split + transpose: W[K,N] fp32 -> hi/lo [N,K] bf16 ----------------
__global__ void split_wT(const float* __restrict__ w, __nv_bfloat16* __restrict__ hi,
                         __nv_bfloat16* __restrict__ lo, int K, int N) {
    __shared__ float t[32][33];
    int z = blockIdx.z;
    w += (size_t)z * K * N;
    hi += (size_t)z * N * K;
    lo += (size_t)z * N * K;
    int n0 = blockIdx.x * 32, k0 = blockIdx.y * 32;
    int tx = threadIdx.x, ty = threadIdx.y;
#pragma unroll
    for (int j = 0; j < 4; j++)
        t[ty + j * 8][tx] = w[(size_t)(k0 + ty + j * 8) * N + n0 + tx];
    __syncthreads();
#pragma unroll
    for (int j = 0; j < 4; j++) {
        int n = n0 + ty + j * 8, k = k0 + tx;
        float v = t[tx][ty + j * 8];
        __nv_bfloat16 h = __float2bfloat16(v);
        hi[(size_t)n * K + k] = h;
        lo[(size_t)n * K + k] = __float2bfloat16(v - __bfloat162float(h));
    }
}

// =================================================================
//            SIMT pieces (attention path + pointwise)
// =================================================================
template <int BM, int BN, int BK, int TM, int TN, int EPI>
__global__ void __launch_bounds__((BM / TM) * (BN / TN))
gemm_k(const float* __restrict__ A, const float* __restrict__ Bm,
       const float* __restrict__ Add, float* __restrict__ C,
       int M, int N, int K, int lda, int ldb, int ldc,
       float alpha, int transB, int causal, int zdiv,
       long long sA1, long long sA2, long long sB1, long long sB2,
       long long sC1, long long sC2) {
    constexpr int NT = (BM / TM) * (BN / TN);
    __shared__ float As[BK][BM + 4];
    __shared__ float Bs[BK][BN];

    int z = blockIdx.z;
    long long zq = z / zdiv, zr = z % zdiv;
    A += zq * sA1 + zr * sA2;
    Bm += zq * sB1 + zr * sB2;
    C += zq * sC1 + zr * sC2;
    if (EPI == 2) Add += zq * sC1 + zr * sC2;

    int row0 = blockIdx.y * BM;
    int col0 = blockIdx.x * BN;
    if (causal == 1 && col0 > row0 + BM - 1) return;
    int Keff = (causal == 2) ? ((row0 + BM < K) ? row0 + BM : K) : K;

    int tid = threadIdx.x;
    int tx = tid % (BN / TN);
    int ty = tid / (BN / TN);

    float acc[TM][TN];
#pragma unroll
    for (int i = 0; i < TM; i++)
#pragma unroll
        for (int j = 0; j < TN; j++) acc[i][j] = 0.f;

    for (int k0 = 0; k0 < Keff; k0 += BK) {
#pragma unroll
        for (int t = tid; t < BM * BK / 4; t += NT) {
            int m = t / (BK / 4);
            int kq = (t % (BK / 4)) * 4;
            float4 v = make_float4(0.f, 0.f, 0.f, 0.f);
            int gr = row0 + m;
            if (gr < M)
                v = *reinterpret_cast<const float4*>(&A[(long long)gr * lda + k0 + kq]);
            As[kq + 0][m] = v.x;
            As[kq + 1][m] = v.y;
            As[kq + 2][m] = v.z;
            As[kq + 3][m] = v.w;
        }
        if (!transB) {
#pragma unroll
            for (int t = tid; t < BK * BN / 4; t += NT) {
                int k = t / (BN / 4);
                int nq = (t % (BN / 4)) * 4;
                int gc = col0 + nq;
                float4 v = make_float4(0.f, 0.f, 0.f, 0.f);
                const float* src = &Bm[(long long)(k0 + k) * ldb + gc];
                if (gc + 3 < N) {
                    v = *reinterpret_cast<const float4*>(src);
                } else {
                    if (gc + 0 < N) v.x = src[0];
                    if (gc + 1 < N) v.y = src[1];
                    if (gc + 2 < N) v.z = src[2];
                    if (gc + 3 < N) v.w = src[3];
                }
                *reinterpret_cast<float4*>(&Bs[k][nq]) = v;
            }
        } else {
#pragma unroll
            for (int t = tid; t < BN * BK / 4; t += NT) {
                int n = t / (BK / 4);
                int kq = (t % (BK / 4)) * 4;
                int gc = col0 + n;
                float4 v = make_float4(0.f, 0.f, 0.f, 0.f);
                if (gc < N)
                    v = *reinterpret_cast<const float4*>(&Bm[(long long)gc * ldb + k0 + kq]);
                Bs[kq + 0][n] = v.x;
                Bs[kq + 1][n] = v.y;
                Bs[kq + 2][n] = v.z;
                Bs[kq + 3][n] = v.w;
            }
        }
        __syncthreads();

#pragma unroll
        for (int kk = 0; kk < BK; kk++) {
            float a[TM], b[TN];
            const float4* a4 = reinterpret_cast<const float4*>(&As[kk][ty * TM]);
            const float4* b4 = reinterpret_cast<const float4*>(&Bs[kk][tx * TN]);
#pragma unroll
            for (int i = 0; i < TM / 4; i++) {
                float4 v = a4[i];
                a[4 * i] = v.x; a[4 * i + 1] = v.y; a[4 * i + 2] = v.z; a[4 * i + 3] = v.w;
            }
#pragma unroll
            for (int j = 0; j < TN / 4; j++) {
                float4 v = b4[j];
                b[4 * j] = v.x; b[4 * j + 1] = v.y; b[4 * j + 2] = v.z; b[4 * j + 3] = v.w;
            }
#pragma unroll
            for (int i = 0; i < TM; i++)
#pragma unroll
                for (int j = 0; j < TN; j++) acc[i][j] += a[i] * b[j];
        }
        __syncthreads();
    }

#pragma unroll
    for (int i = 0; i < TM; i++) {
        int r = row0 + ty * TM + i;
        if (r >= M) continue;
#pragma unroll
        for (int j = 0; j < TN; j++) {
            int c = col0 + tx * TN + j;
            if (c >= N) continue;
            float v = acc[i][j] * alpha;
            if (EPI == 1) v = 0.5f * v * (1.f + erff(v * 0.70710678118654752440f));
            if (EPI == 2) v += Add[(long long)r * ldc + c];
            C[(long long)r * ldc + c] = v;
        }
    }
}

__global__ void embed_kernel(const int* __restrict__ idx,
                             const float* __restrict__ wte,
                             const float* __restrict__ wpe,
                             float* __restrict__ out) {
    int t = blockIdx.x;
    int pos = t % T_;
    int id = idx[t];
    float4 a = reinterpret_cast<const float4*>(wte + (long long)id * E_)[threadIdx.x];
    float4 b = reinterpret_cast<const float4*>(wpe + (long long)pos * E_)[threadIdx.x];
    float4 o;
    o.x = a.x + b.x; o.y = a.y + b.y; o.z = a.z + b.z; o.w = a.w + b.w;
    reinterpret_cast<float4*>(out + (long long)t * E_)[threadIdx.x] = o;
}

__global__ void ln_kernel(const float* __restrict__ x, const float* __restrict__ w,
                          float* __restrict__ out) {
    int row = blockIdx.x;
    float4 v = reinterpret_cast<const float4*>(x + (long long)row * E_)[threadIdx.x];
    float s = v.x + v.y + v.z + v.w;
    float ss = v.x * v.x + v.y * v.y + v.z * v.z + v.w * v.w;
    __shared__ float sh[8];
#pragma unroll
    for (int o = 16; o > 0; o >>= 1) {
        s += __shfl_down_sync(0xffffffffu, s, o);
        ss += __shfl_down_sync(0xffffffffu, ss, o);
    }
    int wid = threadIdx.x >> 5, lane = threadIdx.x & 31;
    if (lane == 0) { sh[wid] = s; sh[4 + wid] = ss; }
    __syncthreads();
    if (threadIdx.x == 0) {
        float ts = sh[0] + sh[1] + sh[2] + sh[3];
        float tss = sh[4] + sh[5] + sh[6] + sh[7];
        float m = ts * (1.f / E_);
        float var = tss * (1.f / E_) - m * m;
        sh[0] = m;
        sh[1] = rsqrtf(var + 1e-5f);
    }
    __syncthreads();
    float m = sh[0], r = sh[1];
    float4 wv = reinterpret_cast<const float4*>(w)[threadIdx.x];
    float4 o;
    o.x = (v.x - m) * r * wv.x;
    o.y = (v.y - m) * r * wv.y;
    o.z = (v.z - m) * r * wv.z;
    o.w = (v.w - m) * r * wv.w;
    reinterpret_cast<float4*>(out + (long long)row * E_)[threadIdx.x] = o;
}

__global__ void softmax_kernel(float* __restrict__ S) {
    int i = blockIdx.x;
    float* row = S + (long long)blockIdx.y * T_ * T_ + (long long)i * T_;
    int n = i + 1;
    __shared__ float sh[8];
    int tid = threadIdx.x, lane = tid & 31, wid = tid >> 5;

    float m = -3.4e38f;
    for (int j = tid; j < n; j += 128) m = fmaxf(m, row[j]);
#pragma unroll
    for (int o = 16; o > 0; o >>= 1) m = fmaxf(m, __shfl_xor_sync(0xffffffffu, m, o));
    if (lane == 0) sh[wid] = m;
    __syncthreads();
    m = fmaxf(fmaxf(sh[0], sh[1]), fmaxf(sh[2], sh[3]));

    float s = 0.f;
    for (int j = tid; j < n; j += 128) {
        float e = expf(row[j] - m);
        row[j] = e;
        s += e;
    }
#pragma unroll
    for (int o = 16; o > 0; o >>= 1) s += __shfl_xor_sync(0xffffffffu, s, o);
    if (lane == 0) sh[4 + wid] = s;
    __syncthreads();
    s = sh[4] + sh[5] + sh[6] + sh[7];
    float inv = 1.f / s;
    for (int j = tid; j < n; j += 128) row[j] *= inv;

    int zend = ((i >> 7) + 1) << 7;
    for (int j = n + tid; j < zend; j += 128) row[j] = 0.f;
}

// =================================================================
//                          host pipeline
// =================================================================
extern "C" void kernel_launch(void* const* d_in, const int* in_sizes, int n_in,
                              void* d_out, int out_size) {
    (void)in_sizes; (void)n_in; (void)out_size;
    const int* idx = (const int*)d_in[0];
    const float* wte = (const float*)d_in[1];
    const float* wpe = (const float*)d_in[2];
    const float* aw = (const float*)d_in[3];
    const float* pw = (const float*)d_in[4];
    const float* fw = (const float*)d_in[5];
    const float* fpw = (const float*)d_in[6];
    const float* l1 = (const float*)d_in[7];
    const float* l2 = (const float*)d_in[8];
    const float* lnf = (const float*)d_in[9];
    float* out = (float*)d_out;

    float *gx, *gh, *gqkv, *gatt, *gy, *gh2;
    __nv_bfloat16 *gah, *gal, *gwh, *gwl;
    cudaGetSymbolAddress((void**)&gx, g_x);
    cudaGetSymbolAddress((void**)&gh, g_h);
    cudaGetSymbolAddress((void**)&gqkv, g_qkv);
    cudaGetSymbolAddress((void**)&gatt, g_att);
    cudaGetSymbolAddress((void**)&gy, g_y);
    cudaGetSymbolAddress((void**)&gh2, g_h2);
    cudaGetSymbolAddress((void**)&gah, g_ah);
    cudaGetSymbolAddress((void**)&gal, g_al);
    cudaGetSymbolAddress((void**)&gwh, g_wh);
    cudaGetSymbolAddress((void**)&gwl, g_wl);

    cudaFuncSetAttribute(gemm_mma<0>, cudaFuncAttributeMaxDynamicSharedMemorySize, SMEM_MMA_BYTES);
    cudaFuncSetAttribute(gemm_mma<1>, cudaFuncAttributeMaxDynamicSharedMemorySize, SMEM_MMA_BYTES);
    cudaFuncSetAttribute(gemm_mma<2>, cudaFuncAttributeMaxDynamicSharedMemorySize, SMEM_MMA_BYTES);

    const long long sQKV = (long long)T_ * 3 * E_;
    const long long sATT1 = (long long)H_ * T_ * T_;
    const long long sATT2 = (long long)T_ * T_;

    // ---- weight conversion (split + transpose to [N,K]) ----
    dim3 b32(32, 8);
    split_wT<<<dim3(3 * E_ / 32, E_ / 32, L_), b32>>>(aw, gwh + OFF_AW, gwl + OFF_AW, E_, 3 * E_);
    split_wT<<<dim3(E_ / 32, E_ / 32, L_), b32>>>(pw, gwh + OFF_PW, gwl + OFF_PW, E_, E_);
    split_wT<<<dim3(4 * E_ / 32, E_ / 32, L_), b32>>>(fw, gwh + OFF_FW, gwl + OFF_FW, E_, 4 * E_);
    split_wT<<<dim3(E_ / 32, 4 * E_ / 32, L_), b32>>>(fpw, gwh + OFF_FPW, gwl + OFF_FPW, 4 * E_, E_);
    split_act<<<(V_ * E_ / 4 + 255) / 256, 256>>>((const float4*)wte, gwh + OFF_WTE, gwl + OFF_WTE, V_ * E_ / 4);

    embed_kernel<<<B_ * T_, 128>>>(idx, wte, wpe, gx);

    const int nME = B_ * T_ * E_ / 4;
    const int nM4E = B_ * T_ * 4 * E_ / 4;

    for (int l = 0; l < L_; l++) {
        // h = LN(x, ln1); qkv = h @ aw[l]
        ln_kernel<<<B_ * T_, 128>>>(gx, l1 + (long long)l * E_, gh);
        split_act<<<(nME + 255) / 256, 256>>>((const float4*)gh, gah, gal, nME);
        gemm_mma<0><<<dim3(12, 32), 256, SMEM_MMA_BYTES>>>(
            gah, gal, gwh + OFF_AW + (size_t)l * 3 * E_ * E_, gwl + OFF_AW + (size_t)l * 3 * E_ * E_,
            nullptr, gqkv, 1536, 512, 1536);

        // attention (SIMT): S = scale*q@k^T ; softmax ; y = att@v
        gemm_k<128, 128, 8, 8, 8, 0><<<dim3(8, 8, B_ * H_), 256>>>(
            gqkv, gqkv + E_, nullptr, gatt,
            1024, 1024, 64, 3 * E_, 3 * E_, 1024, 0.125f, 1, 1, H_,
            sQKV, 64, sQKV, 64, sATT1, sATT2);
        softmax_kernel<<<dim3(T_, B_ * H_), 128>>>(gatt);
        gemm_k<128, 64, 8, 8, 8, 0><<<dim3(1, 8, B_ * H_), 128>>>(
            gatt, gqkv + 2 * E_, nullptr, gy,
            1024, 64, 1024, 1024, 3 * E_, 512, 1.f, 0, 2, H_,
            sATT1, sATT2, sQKV, 64, (long long)T_ * E_, 64);

        // x = x + y @ pw[l]
        split_act<<<(nME + 255) / 256, 256>>>((const float4*)gy, gah, gal, nME);
        gemm_mma<2><<<dim3(4, 32), 256, SMEM_MMA_BYTES>>>(
            gah, gal, gwh + OFF_PW + (size_t)l * E_ * E_, gwl + OFF_PW + (size_t)l * E_ * E_,
            gx, gx, 512, 512, 512);

        // h = LN(x, ln2); h2 = gelu(h @ fw[l])
        ln_kernel<<<B_ * T_, 128>>>(gx, l2 + (long long)l * E_, gh);
        split_act<<<(nME + 255) / 256, 256>>>((const float4*)gh, gah, gal, nME);
        gemm_mma<1><<<dim3(16, 32), 256, SMEM_MMA_BYTES>>>(
            gah, gal, gwh + OFF_FW + (size_t)l * 4 * E_ * E_, gwl + OFF_FW + (size_t)l * 4 * E_ * E_,
            nullptr, gh2, 2048, 512, 2048);

        // x = x + h2 @ fpw[l]
        split_act<<<(nM4E + 255) / 256, 256>>>((const float4*)gh2, gah, gal, nM4E);
        gemm_mma<2><<<dim3(4, 32), 256, SMEM_MMA_BYTES>>>(
            gah, gal, gwh + OFF_FPW + (size_t)l * E_ * 4 * E_, gwl + OFF_FPW + (size_t)l * E_ * 4 * E_,
            gx, gx, 512, 2048, 512);
    }

    // final LN + tied logits: out = LN(x) @ wte^T
    ln_kernel<<<B_ * T_, 128>>>(gx, lnf, gh);
    split_act<<<(nME + 255) / 256, 256>>>((const float4*)gh, gah, gal, nME);
    gemm_mma<0><<<dim3(3, 32), 256, SMEM_MMA_BYTES>>>(
        gah, gal, gwh + OFF_WTE, gwl + OFF_WTE,
        nullptr, out, V_, 512, V_);
}

// round 5
// speedup vs baseline: 3.2655x; 1.6861x over previous
#include <cuda_runtime.h>
#include <cuda_bf16.h>
#include <math.h>
#include <stdint.h>

#define V_ 371
#define E_ 512
#define H_ 8
#define L_ 8
#define B_ 4
#define T_ 1024
#define D_ 64

// ---------------- scratch (static device globals; no allocation) ----------------
__device__ __align__(256) float g_x[B_ * T_ * E_];                 // residual fp32
__device__ __align__(256) __nv_bfloat16 g_lnh[B_ * T_ * E_];       // LN out hi
__device__ __align__(256) __nv_bfloat16 g_lnl[B_ * T_ * E_];       // LN out lo
__device__ __align__(256) __nv_bfloat16 g_qh[B_ * H_ * T_ * D_];   // q hi [bh,t,d] (pre-scaled)
__device__ __align__(256) __nv_bfloat16 g_ql[B_ * H_ * T_ * D_];
__device__ __align__(256) __nv_bfloat16 g_kh[B_ * H_ * T_ * D_];
__device__ __align__(256) __nv_bfloat16 g_kl[B_ * H_ * T_ * D_];
__device__ __align__(256) __nv_bfloat16 g_vh[B_ * H_ * D_ * T_];   // v hi [bh,d,t] (transposed)
__device__ __align__(256) __nv_bfloat16 g_vl[B_ * H_ * D_ * T_];
__device__ __align__(256) __nv_bfloat16 g_yh[B_ * T_ * E_];        // attn out hi
__device__ __align__(256) __nv_bfloat16 g_yl[B_ * T_ * E_];
__device__ __align__(256) __nv_bfloat16 g_h2h[B_ * T_ * 4 * E_];   // MLP hidden hi
__device__ __align__(256) __nv_bfloat16 g_h2l[B_ * T_ * 4 * E_];

// weights, [N,K] K-major per layer, hi & lo
#define OFF_AW 0
#define SZ_AW (L_ * 3 * E_ * E_)
#define OFF_PW (OFF_AW + SZ_AW)
#define SZ_PW (L_ * E_ * E_)
#define OFF_FW (OFF_PW + SZ_PW)
#define SZ_FW (L_ * 4 * E_ * E_)
#define OFF_FPW (OFF_FW + SZ_FW)
#define SZ_FPW (L_ * E_ * 4 * E_)
#define OFF_WTE (OFF_FPW + SZ_FPW)
#define SZ_WTE_PAD (384 * E_)
#define SZ_WALL (OFF_WTE + SZ_WTE_PAD)
__device__ __align__(256) __nv_bfloat16 g_wh[SZ_WALL];
__device__ __align__(256) __nv_bfloat16 g_wl[SZ_WALL];

// =================================================================
//                        small helpers
// =================================================================
__device__ __forceinline__ uint32_t smem_u32(const void* p) {
    uint32_t a;
    asm("{ .reg .u64 t; cvta.to.shared.u64 t, %1; cvt.u32.u64 %0, t; }" : "=r"(a) : "l"(p));
    return a;
}
__device__ __forceinline__ void cpa16(void* sdst, const void* gsrc) {
    uint32_t s = smem_u32(sdst);
    asm volatile("cp.async.cg.shared.global [%0], [%1], 16;" :: "r"(s), "l"(gsrc));
}
__device__ __forceinline__ void mma_bf16(float* c, const uint32_t* a, const uint32_t* b) {
    asm volatile(
        "mma.sync.aligned.m16n8k16.row.col.f32.bf16.bf16.f32 "
        "{%0,%1,%2,%3}, {%4,%5,%6,%7}, {%8,%9}, {%0,%1,%2,%3};"
        : "+f"(c[0]), "+f"(c[1]), "+f"(c[2]), "+f"(c[3])
        : "r"(a[0]), "r"(a[1]), "r"(a[2]), "r"(a[3]), "r"(b[0]), "r"(b[1]));
}
// split pair of fp32 into packed bf16 hi/lo
__device__ __forceinline__ void split2(float x0, float x1, uint32_t& hp, uint32_t& lp) {
    __nv_bfloat16 h0 = __float2bfloat16(x0), h1 = __float2bfloat16(x1);
    __nv_bfloat162 hh(h0, h1);
    hp = *reinterpret_cast<uint32_t*>(&hh);
    __nv_bfloat16 l0 = __float2bfloat16(x0 - __bfloat162float(h0));
    __nv_bfloat16 l1 = __float2bfloat16(x1 - __bfloat162float(h1));
    __nv_bfloat162 ll(l0, l1);
    lp = *reinterpret_cast<uint32_t*>(&ll);
}

// =================================================================
//   HMMA split-bf16 GEMM: C[M,N] = A[M,K] @ B[N,K]^T (+epi)
//   EPI: 0 fp32 out (scalar stores, any ldc), 2 residual add fp32,
//        3 qkv-split writer (q*0.125, k, v^T -> g_q/g_k/g_v),
//        4 GELU + split writer (-> g_h2h/g_h2l, ldc 2048)
// =================================================================
#define SROW 40
#define STILE (128 * SROW)
#define SMEM_MMA_BYTES (2 * 4 * STILE * 2)

template <int EPI>
__global__ void __launch_bounds__(256)
gemm_mma(const __nv_bfloat16* __restrict__ Ah, const __nv_bfloat16* __restrict__ Al,
         const __nv_bfloat16* __restrict__ Bh, const __nv_bfloat16* __restrict__ Bl,
         const float* __restrict__ Add, float* __restrict__ C,
         int N, int K, int ldc) {
    extern __shared__ __nv_bfloat16 smh[];
    int tid = threadIdx.x;
    int wid = tid >> 5, lane = tid & 31;
    int wm = wid >> 1, wn = wid & 1;
    int lr = lane >> 2, lc = lane & 3;

    int m0 = blockIdx.y * 128;
    int n0 = blockIdx.x * 128;

    const __nv_bfloat16* srcs[4] = {
        Ah + (size_t)m0 * K, Al + (size_t)m0 * K,
        Bh + (size_t)n0 * K, Bl + (size_t)n0 * K};

    int lrow = tid >> 1;
    int q0 = (tid & 1) * 2;
    int nch = K >> 5;

    {
#pragma unroll
        for (int t = 0; t < 4; t++) {
            const __nv_bfloat16* sp = srcs[t] + (size_t)lrow * K;
            __nv_bfloat16* dp = smh + t * STILE + lrow * SROW;
            cpa16(dp + q0 * 8, sp + q0 * 8);
            cpa16(dp + (q0 + 1) * 8, sp + (q0 + 1) * 8);
        }
        asm volatile("cp.async.commit_group;");
    }

    float acc[2][8][4];
#pragma unroll
    for (int i = 0; i < 2; i++)
#pragma unroll
        for (int j = 0; j < 8; j++)
#pragma unroll
            for (int r = 0; r < 4; r++) acc[i][j][r] = 0.f;

    for (int c = 0; c < nch; c++) {
        if (c + 1 < nch) {
            int k0 = (c + 1) << 5;
            __nv_bfloat16* sb = smh + ((c + 1) & 1) * 4 * STILE;
#pragma unroll
            for (int t = 0; t < 4; t++) {
                const __nv_bfloat16* sp = srcs[t] + (size_t)lrow * K + k0;
                __nv_bfloat16* dp = sb + t * STILE + lrow * SROW;
                cpa16(dp + q0 * 8, sp + q0 * 8);
                cpa16(dp + (q0 + 1) * 8, sp + (q0 + 1) * 8);
            }
            asm volatile("cp.async.commit_group;");
            asm volatile("cp.async.wait_group 1;");
        } else {
            asm volatile("cp.async.wait_group 0;");
        }
        __syncthreads();

        const __nv_bfloat16* tb = smh + (c & 1) * 4 * STILE;
        const __nv_bfloat16* pAh = tb;
        const __nv_bfloat16* pAl = tb + STILE;
        const __nv_bfloat16* pBh = tb + 2 * STILE;
        const __nv_bfloat16* pBl = tb + 3 * STILE;

#pragma unroll
        for (int ks = 0; ks < 2; ks++) {
            int kc = ks * 16 + lc * 2;
            uint32_t ah[2][4], bh[8][2];
#pragma unroll
            for (int i = 0; i < 2; i++) {
                const __nv_bfloat16* p = pAh + (wm * 32 + i * 16 + lr) * SROW + kc;
                ah[i][0] = *(const uint32_t*)p;
                ah[i][1] = *(const uint32_t*)(p + 8 * SROW);
                ah[i][2] = *(const uint32_t*)(p + 8);
                ah[i][3] = *(const uint32_t*)(p + 8 * SROW + 8);
            }
#pragma unroll
            for (int j = 0; j < 8; j++) {
                const __nv_bfloat16* p = pBh + (wn * 64 + j * 8 + lr) * SROW + kc;
                bh[j][0] = *(const uint32_t*)p;
                bh[j][1] = *(const uint32_t*)(p + 8);
            }
#pragma unroll
            for (int i = 0; i < 2; i++)
#pragma unroll
                for (int j = 0; j < 8; j++) mma_bf16(acc[i][j], ah[i], bh[j]);
            {
                uint32_t bl[8][2];
#pragma unroll
                for (int j = 0; j < 8; j++) {
                    const __nv_bfloat16* p = pBl + (wn * 64 + j * 8 + lr) * SROW + kc;
                    bl[j][0] = *(const uint32_t*)p;
                    bl[j][1] = *(const uint32_t*)(p + 8);
                }
#pragma unroll
                for (int i = 0; i < 2; i++)
#pragma unroll
                    for (int j = 0; j < 8; j++) mma_bf16(acc[i][j], ah[i], bl[j]);
            }
            {
                uint32_t al[2][4];
#pragma unroll
                for (int i = 0; i < 2; i++) {
                    const __nv_bfloat16* p = pAl + (wm * 32 + i * 16 + lr) * SROW + kc;
                    al[i][0] = *(const uint32_t*)p;
                    al[i][1] = *(const uint32_t*)(p + 8 * SROW);
                    al[i][2] = *(const uint32_t*)(p + 8);
                    al[i][3] = *(const uint32_t*)(p + 8 * SROW + 8);
                }
#pragma unroll
                for (int i = 0; i < 2; i++)
#pragma unroll
                    for (int j = 0; j < 8; j++) mma_bf16(acc[i][j], al[i], bh[j]);
            }
        }
        __syncthreads();
    }

    // ---- epilogue ----
#pragma unroll
    for (int i = 0; i < 2; i++) {
#pragma unroll
        for (int half = 0; half < 2; half++) {
            int r = m0 + wm * 32 + i * 16 + lr + half * 8;
#pragma unroll
            for (int j = 0; j < 8; j++) {
                int col = n0 + wn * 64 + j * 8 + lc * 2;
                float v0 = acc[i][j][half * 2 + 0];
                float v1 = acc[i][j][half * 2 + 1];
                if (EPI == 0) {
                    float* crow = C + (size_t)r * ldc;
                    if (col < N) crow[col] = v0;
                    if (col + 1 < N) crow[col + 1] = v1;
                } else if (EPI == 2) {
                    const float* arow = Add + (size_t)r * ldc + col;
                    float2 a = *reinterpret_cast<const float2*>(arow);
                    *reinterpret_cast<float2*>(C + (size_t)r * ldc + col) =
                        make_float2(v0 + a.x, v1 + a.y);
                } else if (EPI == 3) {
                    int b = r >> 10, t = r & 1023;
                    int seg = col >> 9, cc = col & 511;
                    int hh = cc >> 6, d = cc & 63;
                    size_t bht = (((size_t)(b * 8 + hh)) << 10) + t;
                    if (seg == 0) {
                        v0 *= 0.125f; v1 *= 0.125f;
                        uint32_t hp, lp; split2(v0, v1, hp, lp);
                        *reinterpret_cast<uint32_t*>(g_qh + bht * 64 + d) = hp;
                        *reinterpret_cast<uint32_t*>(g_ql + bht * 64 + d) = lp;
                    } else if (seg == 1) {
                        uint32_t hp, lp; split2(v0, v1, hp, lp);
                        *reinterpret_cast<uint32_t*>(g_kh + bht * 64 + d) = hp;
                        *reinterpret_cast<uint32_t*>(g_kl + bht * 64 + d) = lp;
                    } else {
                        size_t vb = (((size_t)(b * 8 + hh)) << 16) + (size_t)d * 1024 + t;
                        __nv_bfloat16 h0 = __float2bfloat16(v0);
                        g_vh[vb] = h0;
                        g_vl[vb] = __float2bfloat16(v0 - __bfloat162float(h0));
                        __nv_bfloat16 h1 = __float2bfloat16(v1);
                        g_vh[vb + 1024] = h1;
                        g_vl[vb + 1024] = __float2bfloat16(v1 - __bfloat162float(h1));
                    }
                } else if (EPI == 4) {
                    v0 = 0.5f * v0 * (1.f + erff(v0 * 0.70710678118654752440f));
                    v1 = 0.5f * v1 * (1.f + erff(v1 * 0.70710678118654752440f));
                    uint32_t hp, lp; split2(v0, v1, hp, lp);
                    size_t off = (size_t)r * 2048 + col;
                    *reinterpret_cast<uint32_t*>(g_h2h + off) = hp;
                    *reinterpret_cast<uint32_t*>(g_h2l + off) = lp;
                }
            }
        }
    }
}

// =================================================================
//    Fused flash attention (HMMA split-bf16, online softmax)
//    grid (8 qblocks, 32 bh), 128 threads.
//    smem: 2 buffers x [Kh|Kl|Vh|Vl] each 64x72 halves = 73728 B.
// =================================================================
#define AT_SMEM 73728

__device__ __forceinline__ void at_load_kv(
    __nv_bfloat16* sm, int tid,
    const __nv_bfloat16* kh, const __nv_bfloat16* kl,
    const __nv_bfloat16* vh, const __nv_bfloat16* vl,
    size_t qkoff, size_t voff, int kb, int bsel) {
    int row = tid >> 1;
    int q0 = (tid & 1) * 4;
    __nv_bfloat16* base = sm + bsel * 18432;
    const __nv_bfloat16* gkh = kh + qkoff + (size_t)(kb * 64 + row) * 64;
    const __nv_bfloat16* gkl = kl + qkoff + (size_t)(kb * 64 + row) * 64;
    const __nv_bfloat16* gvh = vh + voff + (size_t)row * 1024 + kb * 64;
    const __nv_bfloat16* gvl = vl + voff + (size_t)row * 1024 + kb * 64;
#pragma unroll
    for (int c = 0; c < 4; c++) {
        cpa16(base + row * 72 + (q0 + c) * 8, gkh + (q0 + c) * 8);
        cpa16(base + 4608 + row * 72 + (q0 + c) * 8, gkl + (q0 + c) * 8);
        cpa16(base + 9216 + row * 72 + (q0 + c) * 8, gvh + (q0 + c) * 8);
        cpa16(base + 13824 + row * 72 + (q0 + c) * 8, gvl + (q0 + c) * 8);
    }
}

__global__ void __launch_bounds__(128)
flash_attn(const __nv_bfloat16* __restrict__ qh, const __nv_bfloat16* __restrict__ ql,
           const __nv_bfloat16* __restrict__ kh, const __nv_bfloat16* __restrict__ kl,
           const __nv_bfloat16* __restrict__ vh, const __nv_bfloat16* __restrict__ vl,
           __nv_bfloat16* __restrict__ yh, __nv_bfloat16* __restrict__ yl) {
    extern __shared__ __nv_bfloat16 sm[];
    int tid = threadIdx.x, w = tid >> 5, lane = tid & 31;
    int lr = lane >> 2, lc = lane & 3;
    int qb = 7 - blockIdx.x;          // long CTAs launch first
    int bh = blockIdx.y;
    const size_t qkoff = (size_t)bh << 16;   // *65536 = 1024*64
    const size_t voff = (size_t)bh << 16;

    // ---- stage Q (hi at [0,9216), lo at [9216,18432) halves) ----
    {
        const __nv_bfloat16* gq = qh + qkoff + (size_t)(qb * 128 + tid) * 64;
        const __nv_bfloat16* gq2 = ql + qkoff + (size_t)(qb * 128 + tid) * 64;
        __nv_bfloat16* dh = sm + tid * 72;
        __nv_bfloat16* dl = sm + 9216 + tid * 72;
#pragma unroll
        for (int q = 0; q < 8; q++) { cpa16(dh + q * 8, gq + q * 8); cpa16(dl + q * 8, gq2 + q * 8); }
        asm volatile("cp.async.commit_group;");
        asm volatile("cp.async.wait_group 0;");
        __syncthreads();
    }
    uint32_t qfh[2][4][4], qfl[2][4][4];
#pragma unroll
    for (int mt = 0; mt < 2; mt++)
#pragma unroll
        for (int kk = 0; kk < 4; kk++) {
            int r = w * 32 + mt * 16 + lr;
            const __nv_bfloat16* p = sm + r * 72 + kk * 16 + lc * 2;
            qfh[mt][kk][0] = *(const uint32_t*)p;
            qfh[mt][kk][1] = *(const uint32_t*)(p + 8 * 72);
            qfh[mt][kk][2] = *(const uint32_t*)(p + 8);
            qfh[mt][kk][3] = *(const uint32_t*)(p + 8 * 72 + 8);
            const __nv_bfloat16* p2 = p + 9216;
            qfl[mt][kk][0] = *(const uint32_t*)p2;
            qfl[mt][kk][1] = *(const uint32_t*)(p2 + 8 * 72);
            qfl[mt][kk][2] = *(const uint32_t*)(p2 + 8);
            qfl[mt][kk][3] = *(const uint32_t*)(p2 + 8 * 72 + 8);
        }
    __syncthreads();

    float m_[4], l_[4], o[2][8][4];
#pragma unroll
    for (int s = 0; s < 4; s++) { m_[s] = -1e30f; l_[s] = 0.f; }
#pragma unroll
    for (int i = 0; i < 2; i++)
#pragma unroll
        for (int j = 0; j < 8; j++)
#pragma unroll
            for (int r = 0; r < 4; r++) o[i][j][r] = 0.f;

    int nkb = 2 * qb + 2;
    at_load_kv(sm, tid, kh, kl, vh, vl, qkoff, voff, 0, 1);
    asm volatile("cp.async.commit_group;");

    for (int kb = 0; kb < nkb; kb++) {
        if (kb + 1 < nkb) {
            at_load_kv(sm, tid, kh, kl, vh, vl, qkoff, voff, kb + 1, kb & 1);
            asm volatile("cp.async.commit_group;");
            asm volatile("cp.async.wait_group 1;");
        } else {
            asm volatile("cp.async.wait_group 0;");
        }
        __syncthreads();

        const __nv_bfloat16* base = sm + ((kb + 1) & 1) * 18432;
        const __nv_bfloat16* pKh = base;
        const __nv_bfloat16* pKl = base + 4608;
        const __nv_bfloat16* pVh = base + 9216;
        const __nv_bfloat16* pVl = base + 13824;

        float s[2][8][4];
#pragma unroll
        for (int i = 0; i < 2; i++)
#pragma unroll
            for (int j = 0; j < 8; j++)
#pragma unroll
                for (int r = 0; r < 4; r++) s[i][j][r] = 0.f;

        // S = Qh*Kh + Qh*Kl + Ql*Kh
#pragma unroll
        for (int kk = 0; kk < 4; kk++) {
#pragma unroll
            for (int jn = 0; jn < 8; jn++) {
                const __nv_bfloat16* pk = pKh + (jn * 8 + lr) * 72 + kk * 16 + lc * 2;
                uint32_t b0[2] = {*(const uint32_t*)pk, *(const uint32_t*)(pk + 8)};
                const __nv_bfloat16* pk2 = pKl + (jn * 8 + lr) * 72 + kk * 16 + lc * 2;
                uint32_t b1[2] = {*(const uint32_t*)pk2, *(const uint32_t*)(pk2 + 8)};
#pragma unroll
                for (int mt = 0; mt < 2; mt++) {
                    mma_bf16(s[mt][jn], qfh[mt][kk], b0);
                    mma_bf16(s[mt][jn], qfh[mt][kk], b1);
                    mma_bf16(s[mt][jn], qfl[mt][kk], b0);
                }
            }
        }

        // causal mask (only the two diagonal blocks)
        if (kb >= 2 * qb) {
            int rowbase = qb * 128 + w * 32;
            int colbase = kb * 64;
#pragma unroll
            for (int mt = 0; mt < 2; mt++)
#pragma unroll
                for (int jn = 0; jn < 8; jn++)
#pragma unroll
                    for (int idx = 0; idx < 4; idx++) {
                        int row = rowbase + mt * 16 + lr + ((idx >> 1) << 3);
                        int col = colbase + jn * 8 + lc * 2 + (idx & 1);
                        if (col > row) s[mt][jn][idx] = -1e30f;
                    }
        }

        // online softmax
        float scl[4];
#pragma unroll
        for (int sl = 0; sl < 4; sl++) {
            int mt = sl >> 1, h = sl & 1;
            float cm = -1e30f;
#pragma unroll
            for (int jn = 0; jn < 8; jn++)
                cm = fmaxf(cm, fmaxf(s[mt][jn][h * 2], s[mt][jn][h * 2 + 1]));
            cm = fmaxf(cm, __shfl_xor_sync(0xffffffffu, cm, 1));
            cm = fmaxf(cm, __shfl_xor_sync(0xffffffffu, cm, 2));
            float mnew = fmaxf(m_[sl], cm);
            scl[sl] = __expf(m_[sl] - mnew);
            m_[sl] = mnew;
        }
        float rs[4] = {0.f, 0.f, 0.f, 0.f};
#pragma unroll
        for (int mt = 0; mt < 2; mt++)
#pragma unroll
            for (int jn = 0; jn < 8; jn++) {
                s[mt][jn][0] = __expf(s[mt][jn][0] - m_[mt * 2]);
                s[mt][jn][1] = __expf(s[mt][jn][1] - m_[mt * 2]);
                s[mt][jn][2] = __expf(s[mt][jn][2] - m_[mt * 2 + 1]);
                s[mt][jn][3] = __expf(s[mt][jn][3] - m_[mt * 2 + 1]);
                rs[mt * 2] += s[mt][jn][0] + s[mt][jn][1];
                rs[mt * 2 + 1] += s[mt][jn][2] + s[mt][jn][3];
            }
#pragma unroll
        for (int sl = 0; sl < 4; sl++) {
            rs[sl] += __shfl_xor_sync(0xffffffffu, rs[sl], 1);
            rs[sl] += __shfl_xor_sync(0xffffffffu, rs[sl], 2);
            l_[sl] = l_[sl] * scl[sl] + rs[sl];
        }
        // rescale O
#pragma unroll
        for (int mt = 0; mt < 2; mt++)
#pragma unroll
            for (int jn = 0; jn < 8; jn++) {
                o[mt][jn][0] *= scl[mt * 2];
                o[mt][jn][1] *= scl[mt * 2];
                o[mt][jn][2] *= scl[mt * 2 + 1];
                o[mt][jn][3] *= scl[mt * 2 + 1];
            }

        // P·V (3-term), P fragments built from S fragments
#pragma unroll
        for (int kk = 0; kk < 4; kk++) {
            uint32_t pah[2][4], pal[2][4];
#pragma unroll
            for (int mt = 0; mt < 2; mt++) {
                split2(s[mt][2 * kk][0], s[mt][2 * kk][1], pah[mt][0], pal[mt][0]);
                split2(s[mt][2 * kk][2], s[mt][2 * kk][3], pah[mt][1], pal[mt][1]);
                split2(s[mt][2 * kk + 1][0], s[mt][2 * kk + 1][1], pah[mt][2], pal[mt][2]);
                split2(s[mt][2 * kk + 1][2], s[mt][2 * kk + 1][3], pah[mt][3], pal[mt][3]);
            }
#pragma unroll
            for (int jn = 0; jn < 8; jn++) {
                const __nv_bfloat16* pv = pVh + (jn * 8 + lr) * 72 + kk * 16 + lc * 2;
                uint32_t b0[2] = {*(const uint32_t*)pv, *(const uint32_t*)(pv + 8)};
                const __nv_bfloat16* pv2 = pVl + (jn * 8 + lr) * 72 + kk * 16 + lc * 2;
                uint32_t b1[2] = {*(const uint32_t*)pv2, *(const uint32_t*)(pv2 + 8)};
#pragma unroll
                for (int mt = 0; mt < 2; mt++) {
                    mma_bf16(o[mt][jn], pah[mt], b0);
                    mma_bf16(o[mt][jn], pah[mt], b1);
                    mma_bf16(o[mt][jn], pal[mt], b0);
                }
            }
        }
        __syncthreads();
    }

    // ---- epilogue: O/l -> y split ----
    int b = bh >> 3, hhd = bh & 7;
#pragma unroll
    for (int mt = 0; mt < 2; mt++)
#pragma unroll
        for (int h = 0; h < 2; h++) {
            int t = qb * 128 + w * 32 + mt * 16 + lr + h * 8;
            size_t row = (size_t)(b * 1024 + t) * 512 + hhd * 64;
            float inv = 1.f / l_[mt * 2 + h];
#pragma unroll
            for (int jn = 0; jn < 8; jn++) {
                int col = jn * 8 + lc * 2;
                float x0 = o[mt][jn][h * 2] * inv;
                float x1 = o[mt][jn][h * 2 + 1] * inv;
                uint32_t hp, lp;
                split2(x0, x1, hp, lp);
                *reinterpret_cast<uint32_t*>(yh + row + col) = hp;
                *reinterpret_cast<uint32_t*>(yl + row + col) = lp;
            }
        }
}

// ---------------- fp32 -> bf16 hi/lo split (weights/wte only) ----------------
__global__ void split_act(const float4* __restrict__ x, __nv_bfloat16* __restrict__ hi,
                          __nv_bfloat16* __restrict__ lo, int n4) {
    int i = blockIdx.x * blockDim.x + threadIdx.x;
    if (i >= n4) return;
    float4 v = x[i];
    uint32_t hp, lp;
    split2(v.x, v.y, hp, lp);
    reinterpret_cast<uint32_t*>(hi)[2 * i] = hp;
    reinterpret_cast<uint32_t*>(lo)[2 * i] = lp;
    split2(v.z, v.w, hp, lp);
    reinterpret_cast<uint32_t*>(hi)[2 * i + 1] = hp;
    reinterpret_cast<uint32_t*>(lo)[2 * i + 1] = lp;
}

// ---------------- weight split + transpose: W[K,N] fp32 -> hi/lo [N,K] bf16 ----------------
__global__ void split_wT(const float* __restrict__ w, __nv_bfloat16* __restrict__ hi,
                         __nv_bfloat16* __restrict__ lo, int K, int N) {
    __shared__ float t[32][33];
    int z = blockIdx.z;
    w += (size_t)z * K * N;
    hi += (size_t)z * N * K;
    lo += (size_t)z * N * K;
    int n0 = blockIdx.x * 32, k0 = blockIdx.y * 32;
    int tx = threadIdx.x, ty = threadIdx.y;
#pragma unroll
    for (int j = 0; j < 4; j++)
        t[ty + j * 8][tx] = w[(size_t)(k0 + ty + j * 8) * N + n0 + tx];
    __syncthreads();
#pragma unroll
    for (int j = 0; j < 4; j++) {
        int n = n0 + ty + j * 8, k = k0 + tx;
        float v = t[tx][ty + j * 8];
        __nv_bfloat16 h = __float2bfloat16(v);
        hi[(size_t)n * K + k] = h;
        lo[(size_t)n * K + k] = __float2bfloat16(v - __bfloat162float(h));
    }
}

// ---------------- embedding ----------------
__global__ void embed_kernel(const int* __restrict__ idx,
                             const float* __restrict__ wte,
                             const float* __restrict__ wpe,
                             float* __restrict__ out) {
    int t = blockIdx.x;
    int pos = t % T_;
    int id = idx[t];
    float4 a = reinterpret_cast<const float4*>(wte + (long long)id * E_)[threadIdx.x];
    float4 b = reinterpret_cast<const float4*>(wpe + (long long)pos * E_)[threadIdx.x];
    float4 o;
    o.x = a.x + b.x; o.y = a.y + b.y; o.z = a.z + b.z; o.w = a.w + b.w;
    reinterpret_cast<float4*>(out + (long long)t * E_)[threadIdx.x] = o;
}

// ---------------- LayerNorm -> split bf16 ----------------
__global__ void ln_split(const float* __restrict__ x, const float* __restrict__ w,
                         __nv_bfloat16* __restrict__ oh, __nv_bfloat16* __restrict__ ol) {
    int row = blockIdx.x;
    float4 v = reinterpret_cast<const float4*>(x + (long long)row * E_)[threadIdx.x];
    float s = v.x + v.y + v.z + v.w;
    float ss = v.x * v.x + v.y * v.y + v.z * v.z + v.w * v.w;
    __shared__ float sh[8];
#pragma unroll
    for (int o = 16; o > 0; o >>= 1) {
        s += __shfl_down_sync(0xffffffffu, s, o);
        ss += __shfl_down_sync(0xffffffffu, ss, o);
    }
    int wid = threadIdx.x >> 5, lane = threadIdx.x & 31;
    if (lane == 0) { sh[wid] = s; sh[4 + wid] = ss; }
    __syncthreads();
    if (threadIdx.x == 0) {
        float ts = sh[0] + sh[1] + sh[2] + sh[3];
        float tss = sh[4] + sh[5] + sh[6] + sh[7];
        float m = ts * (1.f / E_);
        float var = tss * (1.f / E_) - m * m;
        sh[0] = m;
        sh[1] = rsqrtf(var + 1e-5f);
    }
    __syncthreads();
    float m = sh[0], r = sh[1];
    float4 wv = reinterpret_cast<const float4*>(w)[threadIdx.x];
    float o0 = (v.x - m) * r * wv.x;
    float o1 = (v.y - m) * r * wv.y;
    float o2 = (v.z - m) * r * wv.z;
    float o3 = (v.w - m) * r * wv.w;
    size_t base = (size_t)row * E_ + threadIdx.x * 4;
    uint32_t hp, lp;
    split2(o0, o1, hp, lp);
    *reinterpret_cast<uint32_t*>(oh + base) = hp;
    *reinterpret_cast<uint32_t*>(ol + base) = lp;
    split2(o2, o3, hp, lp);
    *reinterpret_cast<uint32_t*>(oh + base + 2) = hp;
    *reinterpret_cast<uint32_t*>(ol + base + 2) = lp;
}

// =================================================================
//                          host pipeline
// =================================================================
extern "C" void kernel_launch(void* const* d_in, const int* in_sizes, int n_in,
                              void* d_out, int out_size) {
    (void)in_sizes; (void)n_in; (void)out_size;
    const int* idx = (const int*)d_in[0];
    const float* wte = (const float*)d_in[1];
    const float* wpe = (const float*)d_in[2];
    const float* aw = (const float*)d_in[3];
    const float* pw = (const float*)d_in[4];
    const float* fw = (const float*)d_in[5];
    const float* fpw = (const float*)d_in[6];
    const float* l1 = (const float*)d_in[7];
    const float* l2 = (const float*)d_in[8];
    const float* lnf = (const float*)d_in[9];
    float* out = (float*)d_out;

    float* gx;
    __nv_bfloat16 *glnh, *glnl, *gqh, *gql, *gkh, *gkl, *gvh, *gvl, *gyh, *gyl, *gh2h, *gh2l, *gwh, *gwl;
    cudaGetSymbolAddress((void**)&gx, g_x);
    cudaGetSymbolAddress((void**)&glnh, g_lnh);
    cudaGetSymbolAddress((void**)&glnl, g_lnl);
    cudaGetSymbolAddress((void**)&gqh, g_qh);
    cudaGetSymbolAddress((void**)&gql, g_ql);
    cudaGetSymbolAddress((void**)&gkh, g_kh);
    cudaGetSymbolAddress((void**)&gkl, g_kl);
    cudaGetSymbolAddress((void**)&gvh, g_vh);
    cudaGetSymbolAddress((void**)&gvl, g_vl);
    cudaGetSymbolAddress((void**)&gyh, g_yh);
    cudaGetSymbolAddress((void**)&gyl, g_yl);
    cudaGetSymbolAddress((void**)&gh2h, g_h2h);
    cudaGetSymbolAddress((void**)&gh2l, g_h2l);
    cudaGetSymbolAddress((void**)&gwh, g_wh);
    cudaGetSymbolAddress((void**)&gwl, g_wl);

    cudaFuncSetAttribute(gemm_mma<0>, cudaFuncAttributeMaxDynamicSharedMemorySize, SMEM_MMA_BYTES);
    cudaFuncSetAttribute(gemm_mma<2>, cudaFuncAttributeMaxDynamicSharedMemorySize, SMEM_MMA_BYTES);
    cudaFuncSetAttribute(gemm_mma<3>, cudaFuncAttributeMaxDynamicSharedMemorySize, SMEM_MMA_BYTES);
    cudaFuncSetAttribute(gemm_mma<4>, cudaFuncAttributeMaxDynamicSharedMemorySize, SMEM_MMA_BYTES);
    cudaFuncSetAttribute(flash_attn, cudaFuncAttributeMaxDynamicSharedMemorySize, AT_SMEM);

    // ---- weight conversion (split + transpose to [N,K]) ----
    dim3 b32(32, 8);
    split_wT<<<dim3(3 * E_ / 32, E_ / 32, L_), b32>>>(aw, gwh + OFF_AW, gwl + OFF_AW, E_, 3 * E_);
    split_wT<<<dim3(E_ / 32, E_ / 32, L_), b32>>>(pw, gwh + OFF_PW, gwl + OFF_PW, E_, E_);
    split_wT<<<dim3(4 * E_ / 32, E_ / 32, L_), b32>>>(fw, gwh + OFF_FW, gwl + OFF_FW, E_, 4 * E_);
    split_wT<<<dim3(E_ / 32, 4 * E_ / 32, L_), b32>>>(fpw, gwh + OFF_FPW, gwl + OFF_FPW, 4 * E_, E_);
    split_act<<<(V_ * E_ / 4 + 255) / 256, 256>>>((const float4*)wte, gwh + OFF_WTE, gwl + OFF_WTE, V_ * E_ / 4);

    embed_kernel<<<B_ * T_, 128>>>(idx, wte, wpe, gx);

    for (int l = 0; l < L_; l++) {
        // h = LN(x, ln1) -> split
        ln_split<<<B_ * T_, 128>>>(gx, l1 + (long long)l * E_, glnh, glnl);
        // qkv GEMM -> q/k/v split buffers directly
        gemm_mma<3><<<dim3(12, 32), 256, SMEM_MMA_BYTES>>>(
            glnh, glnl, gwh + OFF_AW + (size_t)l * 3 * E_ * E_, gwl + OFF_AW + (size_t)l * 3 * E_ * E_,
            nullptr, gx, 1536, 512, 1536);
        // fused flash attention -> y split
        flash_attn<<<dim3(8, 32), 128, AT_SMEM>>>(gqh, gql, gkh, gkl, gvh, gvl, gyh, gyl);
        // x = x + y @ pw[l]
        gemm_mma<2><<<dim3(4, 32), 256, SMEM_MMA_BYTES>>>(
            gyh, gyl, gwh + OFF_PW + (size_t)l * E_ * E_, gwl + OFF_PW + (size_t)l * E_ * E_,
            gx, gx, 512, 512, 512);
        // h = LN(x, ln2) -> split; h2 = gelu(h @ fw) -> split
        ln_split<<<B_ * T_, 128>>>(gx, l2 + (long long)l * E_, glnh, glnl);
        gemm_mma<4><<<dim3(16, 32), 256, SMEM_MMA_BYTES>>>(
            glnh, glnl, gwh + OFF_FW + (size_t)l * 4 * E_ * E_, gwl + OFF_FW + (size_t)l * 4 * E_ * E_,
            nullptr, gx, 2048, 512, 2048);
        // x = x + h2 @ fpw[l]
        gemm_mma<2><<<dim3(4, 32), 256, SMEM_MMA_BYTES>>>(
            gh2h, gh2l, gwh + OFF_FPW + (size_t)l * E_ * 4 * E_, gwl + OFF_FPW + (size_t)l * E_ * 4 * E_,
            gx, gx, 512, 2048, 512);
    }

    // final LN + tied logits
    ln_split<<<B_ * T_, 128>>>(gx, lnf, glnh, glnl);
    gemm_mma<0><<<dim3(3, 32), 256, SMEM_MMA_BYTES>>>(
        glnh, glnl, gwh + OFF_WTE, gwl + OFF_WTE,
        nullptr, out, V_, 512, V_);
}